// round 6
// baseline (speedup 1.0000x reference)
#include <cuda_runtime.h>
#include <cstdint>
#include <cstddef>

#define NB 4
#define P  2048
#define D  64
#define ITERS   50
#define CHUNKS  64               // row chunks per batch
#define RPC     32               // rows per chunk
// 10 * log2(e)
#define K2E 14.4269504089f
// log2(1/2048 + 1e-8)
#define LOG_MU2 (-10.99997045f)
#define LOG_NU2 (-10.99997045f)
#define NEG_BIG (-3.0e38f)

__device__ __forceinline__ float ex2f(float x) {
    float r; asm("ex2.approx.f32 %0, %1;" : "=f"(r) : "f"(x)); return r;
}
__device__ __forceinline__ float lg2f(float x) {
    float r; asm("lg2.approx.f32 %0, %1;" : "=f"(r) : "f"(x)); return r;
}

// ---------------- static device scratch -----------------------------------
__device__ float g_us2[NB * P];
__device__ float g_vs2[2][NB * P];           // double-buffered v (base-2 scaled)
__device__ float g_xx[NB * P];
__device__ float g_yy[NB * P];
__device__ float g_pm2[NB * CHUNKS * P];     // column partial max (safe path)
__device__ float g_ps2[NB * CHUNKS * P];     // column partial sum
__device__ float g_cp[NB * 1024];
__device__ unsigned g_ticket[NB * 8];

// ---------------- init -------------------------------------------------------
__global__ void init_kernel() {
    int t = blockIdx.x * 256 + threadIdx.x;
    if (t < NB * P) g_vs2[0][t] = 0.0f;
    if (t < NB * 8) g_ticket[t] = 0u;
}

// ---------------- squared norms ----------------------------------------------
__global__ __launch_bounds__(256) void norms_kernel(const float* __restrict__ x,
                                                    const float* __restrict__ y) {
    const int r = blockIdx.x * 256 + threadIdx.x;
    const float4* xr = (const float4*)(x + (size_t)r * D);
    const float4* yr = (const float4*)(y + (size_t)r * D);
    float ax = 0.0f, ay = 0.0f;
#pragma unroll
    for (int t = 0; t < D / 4; t++) {
        float4 a = xr[t], b = yr[t];
        ax = fmaf(a.x, a.x, ax); ax = fmaf(a.y, a.y, ax);
        ax = fmaf(a.z, a.z, ax); ax = fmaf(a.w, a.w, ax);
        ay = fmaf(b.x, b.x, ay); ay = fmaf(b.y, b.y, ay);
        ay = fmaf(b.z, b.z, ay); ay = fmaf(b.w, b.w, ay);
    }
    g_xx[r] = ax;
    g_yy[r] = ay;
}

// ---------------- C = xx_i + yy_j - 2*x.y ---------------------------------------
__global__ __launch_bounds__(256) void c_kernel(const float* __restrict__ x,
                                                const float* __restrict__ y,
                                                float* __restrict__ C) {
    __shared__ float Xs[64][68];
    __shared__ float Ys[64][68];
    const int tx = threadIdx.x, ty = threadIdx.y;
    const int tid = ty * 16 + tx;
    const int n  = blockIdx.z;
    const int i0 = blockIdx.y * 64;
    const int j0 = blockIdx.x * 64;

    {
        const int r  = tid >> 2;
        const int c4 = tid & 3;
        const float* xg = x + ((size_t)n * P + i0 + r) * D;
        const float* yg = y + ((size_t)n * P + j0 + r) * D;
#pragma unroll
        for (int q = 0; q < 4; q++) {
            int col = c4 * 16 + q * 4;
            *(float4*)&Xs[r][col] = *(const float4*)(xg + col);
            *(float4*)&Ys[r][col] = *(const float4*)(yg + col);
        }
    }
    __syncthreads();

    float acc[4][4];
#pragma unroll
    for (int a = 0; a < 4; a++)
#pragma unroll
        for (int b = 0; b < 4; b++) acc[a][b] = 0.0f;

#pragma unroll
    for (int k = 0; k < D; k += 4) {
        float4 xa[4], yb[4];
#pragma unroll
        for (int a = 0; a < 4; a++) xa[a] = *(float4*)&Xs[ty * 4 + a][k];
#pragma unroll
        for (int b = 0; b < 4; b++) yb[b] = *(float4*)&Ys[tx * 4 + b][k];
#pragma unroll
        for (int a = 0; a < 4; a++)
#pragma unroll
            for (int b = 0; b < 4; b++) {
                acc[a][b] = fmaf(xa[a].x, yb[b].x, acc[a][b]);
                acc[a][b] = fmaf(xa[a].y, yb[b].y, acc[a][b]);
                acc[a][b] = fmaf(xa[a].z, yb[b].z, acc[a][b]);
                acc[a][b] = fmaf(xa[a].w, yb[b].w, acc[a][b]);
            }
    }

    float yyv[4];
#pragma unroll
    for (int b = 0; b < 4; b++) yyv[b] = g_yy[(n << 11) + j0 + tx * 4 + b];

    float* Cb = C + (size_t)n * P * P;
#pragma unroll
    for (int a = 0; a < 4; a++) {
        float xxv = g_xx[(n << 11) + i0 + ty * 4 + a];
        float4 o;
        o.x = fmaf(-2.0f, acc[a][0], xxv + yyv[0]);
        o.y = fmaf(-2.0f, acc[a][1], xxv + yyv[1]);
        o.z = fmaf(-2.0f, acc[a][2], xxv + yyv[2]);
        o.w = fmaf(-2.0f, acc[a][3], xxv + yyv[3]);
        *(float4*)&Cb[(size_t)(i0 + ty * 4 + a) * P + j0 + tx * 4] = o;
    }
}

// ---------------- LSE helper (safe path) --------------------------------------------
__device__ __forceinline__ void lse_group(float4 c, float vx, float vy, float vz, float vw,
                                          float& m, float& s) {
    float b0 = fmaf(c.x, -K2E, vx);
    float b1 = fmaf(c.y, -K2E, vy);
    float b2 = fmaf(c.z, -K2E, vz);
    float b3 = fmaf(c.w, -K2E, vw);
    float cm = fmaxf(fmaxf(b0, b1), fmaxf(b2, b3));
    float mn = fmaxf(m, cm);
    s = fmaf(s, ex2f(m - mn),
             ex2f(b0 - mn) + ex2f(b1 - mn) + ex2f(b2 - mn) + ex2f(b3 - mn));
    m = mn;
}
__device__ __forceinline__ void lse1(float b, float& m, float& s) {
    float mn = fmaxf(m, b);
    s = fmaf(s, ex2f(m - mn), ex2f(b - mn));
    m = mn;
}

// ---------------- fused iteration: u update + col partials + v combine --------------
// grid = NB*CHUNKS = 256 blocks, 256 threads. Each block owns 32 rows of one batch.
__global__ __launch_bounds__(256) void fused_iter(const float* __restrict__ C, int it) {
    __shared__ float vs[P];
    __shared__ float us_sh[RPC];
    __shared__ unsigned last8[8];
    const int tid  = threadIdx.x;
    const int lane = tid & 31;
    const int warp = tid >> 5;
    const int n     = blockIdx.x >> 6;
    const int chunk = blockIdx.x & (CHUNKS - 1);
    const int i0    = chunk << 5;
    const bool fast = (it >= 2);

    const float* vsrc = g_vs2[it & 1] + (n << 11);
    float* vdst_g = g_vs2[(it + 1) & 1] + (n << 11);

    // ---- phase 0: v into smem -------------------------------------------------
    {
        const float4* s4 = (const float4*)vsrc;
        float4* d4 = (float4*)vs;
#pragma unroll
        for (int t = tid; t < P / 4; t += 256) d4[t] = s4[t];
    }
    __syncthreads();

    // ---- phase 1: u update for my 32 rows (4 rows per warp) --------------------
    const float4* V4 = (const float4*)vs;
#pragma unroll
    for (int rr = 0; rr < 4; rr++) {
        const int row  = i0 + warp * 4 + rr;
        const int grow = (n << 11) + row;
        const float4* Crow = (const float4*)(C + ((size_t)n * P + row) * P);
        if (fast) {
            const float uprev = g_us2[grow];
            const float ref = LOG_MU2 - uprev;
            float s0 = 0.0f, s1 = 0.0f, s2 = 0.0f, s3 = 0.0f;
#pragma unroll
            for (int k = 0; k < 16; k++) {
                const int t = lane + k * 32;
                float4 c  = Crow[t];
                float4 vv = V4[t];
                s0 += ex2f(fmaf(c.x, -K2E, vv.x) - ref);
                s1 += ex2f(fmaf(c.y, -K2E, vv.y) - ref);
                s2 += ex2f(fmaf(c.z, -K2E, vv.z) - ref);
                s3 += ex2f(fmaf(c.w, -K2E, vv.w) - ref);
            }
            float s = (s0 + s1) + (s2 + s3);
#pragma unroll
            for (int o = 16; o; o >>= 1)
                s += __shfl_xor_sync(0xffffffffu, s, o);
            if (lane == 0) {
                float un = uprev - lg2f(s);
                g_us2[grow] = un;
                us_sh[row - i0] = un;
            }
        } else {
            float m0 = NEG_BIG, s0 = 0.0f, m1 = NEG_BIG, s1 = 0.0f;
#pragma unroll
            for (int k = 0; k < 8; k++) {
                const int t0 = lane + k * 64;
                const int t1 = t0 + 32;
                float4 c0 = Crow[t0];
                float4 c1 = Crow[t1];
                float4 v0 = V4[t0];
                float4 v1 = V4[t1];
                lse_group(c0, v0.x, v0.y, v0.z, v0.w, m0, s0);
                lse_group(c1, v1.x, v1.y, v1.z, v1.w, m1, s1);
            }
            float m = fmaxf(m0, m1);
            float s = s0 * ex2f(m0 - m) + s1 * ex2f(m1 - m);
#pragma unroll
            for (int o = 16; o; o >>= 1) {
                float mo = __shfl_xor_sync(0xffffffffu, m, o);
                float so = __shfl_xor_sync(0xffffffffu, s, o);
                float mn = fmaxf(m, mo);
                s = s * ex2f(m - mn) + so * ex2f(mo - mn);
                m = mn;
            }
            if (lane == 0) {
                float un = LOG_MU2 - (m + lg2f(s));
                g_us2[grow] = un;
                us_sh[row - i0] = un;
            }
        }
    }
    __syncthreads();

    // ---- phase 2: column partials over my 32 rows (slice is cache-hot) ----------
    const int jA = tid << 2;              // cols 0..1023
    const int jB = 1024 + (tid << 2);     // cols 1024..2047
    const float4* Crow0 = (const float4*)(C + ((size_t)n * P + i0) * P);
    const size_t pbase = ((size_t)(n * CHUNKS + chunk)) * P;

    if (fast) {
        const float rA0 = LOG_NU2 - vs[jA];
        const float rA1 = LOG_NU2 - vs[jA + 1];
        const float rA2 = LOG_NU2 - vs[jA + 2];
        const float rA3 = LOG_NU2 - vs[jA + 3];
        const float rB0 = LOG_NU2 - vs[jB];
        const float rB1 = LOG_NU2 - vs[jB + 1];
        const float rB2 = LOG_NU2 - vs[jB + 2];
        const float rB3 = LOG_NU2 - vs[jB + 3];
        float a0 = 0, a1 = 0, a2 = 0, a3 = 0;
        float b0 = 0, b1 = 0, b2 = 0, b3 = 0;
#pragma unroll 4
        for (int i = 0; i < RPC; i++) {
            float4 ca = Crow0[(size_t)i * (P / 4) + tid];
            float4 cb = Crow0[(size_t)i * (P / 4) + 256 + tid];
            const float ui = us_sh[i];
            a0 += ex2f(fmaf(ca.x, -K2E, ui) - rA0);
            a1 += ex2f(fmaf(ca.y, -K2E, ui) - rA1);
            a2 += ex2f(fmaf(ca.z, -K2E, ui) - rA2);
            a3 += ex2f(fmaf(ca.w, -K2E, ui) - rA3);
            b0 += ex2f(fmaf(cb.x, -K2E, ui) - rB0);
            b1 += ex2f(fmaf(cb.y, -K2E, ui) - rB1);
            b2 += ex2f(fmaf(cb.z, -K2E, ui) - rB2);
            b3 += ex2f(fmaf(cb.w, -K2E, ui) - rB3);
        }
        float4 oa = {a0, a1, a2, a3};
        float4 ob = {b0, b1, b2, b3};
        *(float4*)&g_ps2[pbase + jA] = oa;
        *(float4*)&g_ps2[pbase + jB] = ob;
    } else {
        float mA[4], sA[4], mB[4], sB[4];
#pragma unroll
        for (int q = 0; q < 4; q++) {
            mA[q] = NEG_BIG; sA[q] = 0.0f;
            mB[q] = NEG_BIG; sB[q] = 0.0f;
        }
#pragma unroll 4
        for (int i = 0; i < RPC; i++) {
            float4 ca = Crow0[(size_t)i * (P / 4) + tid];
            float4 cb = Crow0[(size_t)i * (P / 4) + 256 + tid];
            const float ui = us_sh[i];
            lse1(fmaf(ca.x, -K2E, ui), mA[0], sA[0]);
            lse1(fmaf(ca.y, -K2E, ui), mA[1], sA[1]);
            lse1(fmaf(ca.z, -K2E, ui), mA[2], sA[2]);
            lse1(fmaf(ca.w, -K2E, ui), mA[3], sA[3]);
            lse1(fmaf(cb.x, -K2E, ui), mB[0], sB[0]);
            lse1(fmaf(cb.y, -K2E, ui), mB[1], sB[1]);
            lse1(fmaf(cb.z, -K2E, ui), mB[2], sB[2]);
            lse1(fmaf(cb.w, -K2E, ui), mB[3], sB[3]);
        }
        float4 oma = {mA[0], mA[1], mA[2], mA[3]};
        float4 osa = {sA[0], sA[1], sA[2], sA[3]};
        float4 omb = {mB[0], mB[1], mB[2], mB[3]};
        float4 osb = {sB[0], sB[1], sB[2], sB[3]};
        *(float4*)&g_pm2[pbase + jA] = oma;
        *(float4*)&g_ps2[pbase + jA] = osa;
        *(float4*)&g_pm2[pbase + jB] = omb;
        *(float4*)&g_ps2[pbase + jB] = osb;
    }

    // ---- phase 3: distributed ticket combine -> v_{t+1} -------------------------
    __threadfence();
    if (tid < 8) last8[tid] = atomicAdd(&g_ticket[n * 8 + tid], 1u);
    __syncthreads();

#pragma unroll
    for (int g = 0; g < 8; g++) {
        if (last8[g] == CHUNKS - 1) {
            __threadfence();
            const int j = g * 256 + tid;
            if (fast) {
                float ss = 0.0f;
#pragma unroll
                for (int c = 0; c < CHUNKS; c++)
                    ss += __ldcg(&g_ps2[((size_t)(n * CHUNKS + c)) * P + j]);
                vdst_g[j] = vs[j] - lg2f(ss);
            } else {
                float mm = NEG_BIG;
#pragma unroll
                for (int c = 0; c < CHUNKS; c++)
                    mm = fmaxf(mm, __ldcg(&g_pm2[((size_t)(n * CHUNKS + c)) * P + j]));
                float ss = 0.0f;
#pragma unroll
                for (int c = 0; c < CHUNKS; c++) {
                    size_t idx = ((size_t)(n * CHUNKS + c)) * P + j;
                    ss += __ldcg(&g_ps2[idx]) * ex2f(__ldcg(&g_pm2[idx]) - mm);
                }
                vdst_g[j] = LOG_NU2 - (mm + lg2f(ss));
            }
            __syncthreads();
            if (tid == 0) g_ticket[n * 8 + g] = 0u;
        }
    }
}

// ---------------- pi + cost partials ----------------------------------------------
__global__ __launch_bounds__(256) void pi_cost(const float* __restrict__ C,
                                               float* __restrict__ pi) {
    __shared__ float red[256];
    const int b = blockIdx.x;
    const int n = b >> 10;
    const float4* C4 = (const float4*)C;
    float4* P4 = (float4*)pi;
    const float4* V4 = (const float4*)(g_vs2[0] + (n << 11));   // final v in buffer 0
    const size_t base = (size_t)b * 1024;

    float acc = 0.0f;
#pragma unroll
    for (int p = 0; p < 4; p++) {
        size_t f4 = base + (size_t)p * 256 + threadIdx.x;
        float4 c = C4[f4];
        int ig = (int)(f4 >> 9);
        float u = g_us2[ig];
        float4 vv = V4[f4 & (P / 4 - 1)];
        float4 pv;
        pv.x = ex2f(fmaf(c.x, -K2E, u + vv.x));
        pv.y = ex2f(fmaf(c.y, -K2E, u + vv.y));
        pv.z = ex2f(fmaf(c.z, -K2E, u + vv.z));
        pv.w = ex2f(fmaf(c.w, -K2E, u + vv.w));
        P4[f4] = pv;
        acc += pv.x * c.x + pv.y * c.y + pv.z * c.z + pv.w * c.w;
    }
    red[threadIdx.x] = acc;
    __syncthreads();
#pragma unroll
    for (int o = 128; o; o >>= 1) {
        if (threadIdx.x < o) red[threadIdx.x] += red[threadIdx.x + o];
        __syncthreads();
    }
    if (threadIdx.x == 0) g_cp[b] = red[0];
}

__global__ __launch_bounds__(256) void cost_combine(float* __restrict__ cost) {
    __shared__ float red[256];
    const int n = blockIdx.x;
    float a = 0.0f;
#pragma unroll
    for (int q = 0; q < 4; q++)
        a += g_cp[n * 1024 + q * 256 + threadIdx.x];
    red[threadIdx.x] = a;
    __syncthreads();
#pragma unroll
    for (int o = 128; o; o >>= 1) {
        if (threadIdx.x < o) red[threadIdx.x] += red[threadIdx.x + o];
        __syncthreads();
    }
    if (threadIdx.x == 0) cost[n] = red[0];
}

// ---------------- launch --------------------------------------------------------------
extern "C" void kernel_launch(void* const* d_in, const int* in_sizes, int n_in,
                              void* d_out, int out_size) {
    const float* x = (const float*)d_in[0];
    const float* y = (const float*)d_in[1];
    float* out  = (float*)d_out;
    float* cost = out;
    float* pi   = out + NB;
    float* C    = out + NB + (size_t)NB * P * P;

    init_kernel<<<32, 256>>>();
    norms_kernel<<<NB * P / 256, 256>>>(x, y);
    c_kernel<<<dim3(P / 64, P / 64, NB), dim3(16, 16)>>>(x, y, C);

    for (int it = 0; it < ITERS; it++)
        fused_iter<<<NB * CHUNKS, 256>>>(C, it);

    pi_cost<<<NB * 1024, 256>>>(C, pi);
    cost_combine<<<NB, 256>>>(cost);
}

// round 7
// speedup vs baseline: 1.0425x; 1.0425x over previous
#include <cuda_runtime.h>
#include <cuda_bf16.h>
#include <cstdint>
#include <cstddef>

#define NB 4
#define P  2048
#define D  64
#define ITERS   50
// safe col pass geometry (it < 2)
#define RCH_S   32
#define JB_S    4
// fast col pass geometry (it >= 2)
#define RCH_F   64
#define CHK_F   32               // rows per fast chunk
#define JB_F    2
// 10 * log2(e)
#define K2E 14.4269504089f
// log2(1/2048 + 1e-8)
#define LOG_MU2 (-10.99997045f)
#define LOG_NU2 (-10.99997045f)
#define NEG_BIG (-3.0e38f)

__device__ __forceinline__ float ex2f(float x) {
    float r; asm("ex2.approx.f32 %0, %1;" : "=f"(r) : "f"(x)); return r;
}
__device__ __forceinline__ float lg2f(float x) {
    float r; asm("lg2.approx.f32 %0, %1;" : "=f"(r) : "f"(x)); return r;
}

// ---------------- static device scratch -----------------------------------
__device__ float g_us2[NB * P];
__device__ float g_vs2[NB * P];
__device__ float g_f[NB * P];                   // 1/s_i per row (fast path)
__device__ float g_xx[NB * P];
__device__ float g_yy[NB * P];
__device__ float g_pm2[NB * RCH_S * P];         // safe col partial max
__device__ float g_ps2[NB * RCH_F * P];         // col partial sums (both paths)
__device__ float g_cp[NB * 1024];
__device__ unsigned g_tick_s[NB * JB_S];
__device__ unsigned g_tick_f[NB * JB_F];
__device__ __nv_bfloat16 g_E[(size_t)NB * P * P];   // 33.5 MB exp-term scratch

// ---------------- init -------------------------------------------------------
__global__ void init_kernel() {
    int t = blockIdx.x * 256 + threadIdx.x;
    if (t < NB * P) g_vs2[t] = 0.0f;
    if (t < NB * JB_S) g_tick_s[t] = 0u;
    if (t < NB * JB_F) g_tick_f[t] = 0u;
}

// ---------------- squared norms ----------------------------------------------
__global__ __launch_bounds__(256) void norms_kernel(const float* __restrict__ x,
                                                    const float* __restrict__ y) {
    const int r = blockIdx.x * 256 + threadIdx.x;
    const float4* xr = (const float4*)(x + (size_t)r * D);
    const float4* yr = (const float4*)(y + (size_t)r * D);
    float ax = 0.0f, ay = 0.0f;
#pragma unroll
    for (int t = 0; t < D / 4; t++) {
        float4 a = xr[t], b = yr[t];
        ax = fmaf(a.x, a.x, ax); ax = fmaf(a.y, a.y, ax);
        ax = fmaf(a.z, a.z, ax); ax = fmaf(a.w, a.w, ax);
        ay = fmaf(b.x, b.x, ay); ay = fmaf(b.y, b.y, ay);
        ay = fmaf(b.z, b.z, ay); ay = fmaf(b.w, b.w, ay);
    }
    g_xx[r] = ax;
    g_yy[r] = ay;
}

// ---------------- C = xx_i + yy_j - 2*x.y ---------------------------------------
__global__ __launch_bounds__(256) void c_kernel(const float* __restrict__ x,
                                                const float* __restrict__ y,
                                                float* __restrict__ C) {
    __shared__ float Xs[64][68];
    __shared__ float Ys[64][68];
    const int tx = threadIdx.x, ty = threadIdx.y;
    const int tid = ty * 16 + tx;
    const int n  = blockIdx.z;
    const int i0 = blockIdx.y * 64;
    const int j0 = blockIdx.x * 64;

    {
        const int r  = tid >> 2;
        const int c4 = tid & 3;
        const float* xg = x + ((size_t)n * P + i0 + r) * D;
        const float* yg = y + ((size_t)n * P + j0 + r) * D;
#pragma unroll
        for (int q = 0; q < 4; q++) {
            int col = c4 * 16 + q * 4;
            *(float4*)&Xs[r][col] = *(const float4*)(xg + col);
            *(float4*)&Ys[r][col] = *(const float4*)(yg + col);
        }
    }
    __syncthreads();

    float acc[4][4];
#pragma unroll
    for (int a = 0; a < 4; a++)
#pragma unroll
        for (int b = 0; b < 4; b++) acc[a][b] = 0.0f;

#pragma unroll
    for (int k = 0; k < D; k += 4) {
        float4 xa[4], yb[4];
#pragma unroll
        for (int a = 0; a < 4; a++) xa[a] = *(float4*)&Xs[ty * 4 + a][k];
#pragma unroll
        for (int b = 0; b < 4; b++) yb[b] = *(float4*)&Ys[tx * 4 + b][k];
#pragma unroll
        for (int a = 0; a < 4; a++)
#pragma unroll
            for (int b = 0; b < 4; b++) {
                acc[a][b] = fmaf(xa[a].x, yb[b].x, acc[a][b]);
                acc[a][b] = fmaf(xa[a].y, yb[b].y, acc[a][b]);
                acc[a][b] = fmaf(xa[a].z, yb[b].z, acc[a][b]);
                acc[a][b] = fmaf(xa[a].w, yb[b].w, acc[a][b]);
            }
    }

    float yyv[4];
#pragma unroll
    for (int b = 0; b < 4; b++) yyv[b] = g_yy[(n << 11) + j0 + tx * 4 + b];

    float* Cb = C + (size_t)n * P * P;
#pragma unroll
    for (int a = 0; a < 4; a++) {
        float xxv = g_xx[(n << 11) + i0 + ty * 4 + a];
        float4 o;
        o.x = fmaf(-2.0f, acc[a][0], xxv + yyv[0]);
        o.y = fmaf(-2.0f, acc[a][1], xxv + yyv[1]);
        o.z = fmaf(-2.0f, acc[a][2], xxv + yyv[2]);
        o.w = fmaf(-2.0f, acc[a][3], xxv + yyv[3]);
        *(float4*)&Cb[(size_t)(i0 + ty * 4 + a) * P + j0 + tx * 4] = o;
    }
}

// ---------------- safe LSE helper -------------------------------------------------
__device__ __forceinline__ void lse_group(float4 c, float vx, float vy, float vz, float vw,
                                          float& m, float& s) {
    float b0 = fmaf(c.x, -K2E, vx);
    float b1 = fmaf(c.y, -K2E, vy);
    float b2 = fmaf(c.z, -K2E, vz);
    float b3 = fmaf(c.w, -K2E, vw);
    float cm = fmaxf(fmaxf(b0, b1), fmaxf(b2, b3));
    float mn = fmaxf(m, cm);
    s = fmaf(s, ex2f(m - mn),
             ex2f(b0 - mn) + ex2f(b1 - mn) + ex2f(b2 - mn) + ex2f(b3 - mn));
    m = mn;
}

// ================ SAFE path kernels (it < 2), as proven in R5 ======================
__global__ __launch_bounds__(256) void row_safe(const float* __restrict__ C) {
    __shared__ float vs[P];
    const int lane = threadIdx.x & 31;
    const int warp = threadIdx.x >> 5;
    const int row  = blockIdx.x * 8 + warp;
    const int n    = row >> 11;
    {
        const float4* src = (const float4*)(g_vs2 + (n << 11));
        float4* dst = (float4*)vs;
#pragma unroll
        for (int t = threadIdx.x; t < P / 4; t += 256) dst[t] = src[t];
    }
    __syncthreads();
    const float4* Crow = (const float4*)(C + (size_t)row * P);
    const float4* V4   = (const float4*)vs;
    float m0 = NEG_BIG, s0 = 0.0f, m1 = NEG_BIG, s1 = 0.0f;
#pragma unroll
    for (int k = 0; k < 8; k++) {
        const int t0 = lane + k * 64;
        const int t1 = t0 + 32;
        float4 c0 = Crow[t0];
        float4 c1 = Crow[t1];
        float4 v0 = V4[t0];
        float4 v1 = V4[t1];
        lse_group(c0, v0.x, v0.y, v0.z, v0.w, m0, s0);
        lse_group(c1, v1.x, v1.y, v1.z, v1.w, m1, s1);
    }
    float m = fmaxf(m0, m1);
    float s = s0 * ex2f(m0 - m) + s1 * ex2f(m1 - m);
#pragma unroll
    for (int o = 16; o; o >>= 1) {
        float mo = __shfl_xor_sync(0xffffffffu, m, o);
        float so = __shfl_xor_sync(0xffffffffu, s, o);
        float mn = fmaxf(m, mo);
        s = s * ex2f(m - mn) + so * ex2f(mo - mn);
        m = mn;
    }
    if (lane == 0) g_us2[row] = LOG_MU2 - (m + lg2f(s));
}

__global__ __launch_bounds__(256) void col_safe(const float* __restrict__ C) {
    __shared__ float us[P / RCH_S];
    __shared__ unsigned lastv;
    const int b     = blockIdx.x;
    const int jb    = b & (JB_S - 1);
    const int chunk = (b >> 2) & (RCH_S - 1);
    const int n     = b >> 7;
    const int j0    = (jb << 9) + (threadIdx.x << 1);
    const int i0    = chunk << 6;

    if (threadIdx.x < P / RCH_S)
        us[threadIdx.x] = g_us2[(n << 11) + i0 + threadIdx.x];
    __syncthreads();

    const float2* Cc = (const float2*)(C + (size_t)n * P * P + (size_t)i0 * P) + (j0 >> 1);
    const size_t po = ((size_t)n * RCH_S + chunk) * P + j0;

    float m0 = NEG_BIG, s0 = 0.0f, m1 = NEG_BIG, s1 = 0.0f;
#pragma unroll
    for (int i = 0; i < P / RCH_S; i += 4) {
        float2 r0 = Cc[(size_t)(i + 0) * (P / 2)];
        float2 r1 = Cc[(size_t)(i + 1) * (P / 2)];
        float2 r2 = Cc[(size_t)(i + 2) * (P / 2)];
        float2 r3 = Cc[(size_t)(i + 3) * (P / 2)];
        float4 c0 = {r0.x, r1.x, r2.x, r3.x};
        float4 c1 = {r0.y, r1.y, r2.y, r3.y};
        lse_group(c0, us[i], us[i + 1], us[i + 2], us[i + 3], m0, s0);
        lse_group(c1, us[i], us[i + 1], us[i + 2], us[i + 3], m1, s1);
    }
    g_pm2[po] = m0;     g_ps2[po] = s0;
    g_pm2[po + 1] = m1; g_ps2[po + 1] = s1;

    __threadfence();
    if (threadIdx.x == 0) lastv = atomicAdd(&g_tick_s[n * JB_S + jb], 1u);
    __syncthreads();
    if (lastv == RCH_S - 1) {
        __threadfence();
#pragma unroll
        for (int cc = 0; cc < 2; cc++) {
            const int j = j0 + cc;
            float mm = NEG_BIG;
#pragma unroll
            for (int c = 0; c < RCH_S; c++)
                mm = fmaxf(mm, __ldcg(&g_pm2[((size_t)n * RCH_S + c) * P + j]));
            float ss = 0.0f;
#pragma unroll
            for (int c = 0; c < RCH_S; c++) {
                size_t idx = ((size_t)n * RCH_S + c) * P + j;
                ss += __ldcg(&g_ps2[idx]) * ex2f(__ldcg(&g_pm2[idx]) - mm);
            }
            g_vs2[(n << 11) + j] = LOG_NU2 - (mm + lg2f(ss));
        }
        if (threadIdx.x == 0) g_tick_s[n * JB_S + jb] = 0u;
    }
}

// ================ FAST path kernels (it >= 2) ======================================
// row: u update + write e_ij (bf16) + f_i = 1/s_i
__global__ __launch_bounds__(256) void row_fast(const float* __restrict__ C) {
    __shared__ float vs[P];
    const int lane = threadIdx.x & 31;
    const int warp = threadIdx.x >> 5;
    const int row  = blockIdx.x * 8 + warp;
    const int n    = row >> 11;
    {
        const float4* src = (const float4*)(g_vs2 + (n << 11));
        float4* dst = (float4*)vs;
#pragma unroll
        for (int t = threadIdx.x; t < P / 4; t += 256) dst[t] = src[t];
    }
    __syncthreads();

    const float4* Crow = (const float4*)(C + (size_t)row * P);
    const float4* V4   = (const float4*)vs;
    __nv_bfloat16* Erow = g_E + (size_t)row * P;

    const float uprev = g_us2[row];
    const float ref   = LOG_MU2 - uprev;
    float s0 = 0.0f, s1 = 0.0f, s2 = 0.0f, s3 = 0.0f;
#pragma unroll
    for (int k = 0; k < 16; k++) {
        const int t = lane + k * 32;
        float4 c  = Crow[t];
        float4 vv = V4[t];
        float e0 = ex2f(fmaf(c.x, -K2E, vv.x) - ref);
        float e1 = ex2f(fmaf(c.y, -K2E, vv.y) - ref);
        float e2 = ex2f(fmaf(c.z, -K2E, vv.z) - ref);
        float e3 = ex2f(fmaf(c.w, -K2E, vv.w) - ref);
        s0 += e0; s1 += e1; s2 += e2; s3 += e3;
        __nv_bfloat162 h01 = __float22bfloat162_rn(make_float2(e0, e1));
        __nv_bfloat162 h23 = __float22bfloat162_rn(make_float2(e2, e3));
        uint2 pk;
        pk.x = *(uint32_t*)&h01;
        pk.y = *(uint32_t*)&h23;
        *(uint2*)&Erow[t << 2] = pk;
    }
    float s = (s0 + s1) + (s2 + s3);
#pragma unroll
    for (int o = 16; o; o >>= 1)
        s += __shfl_xor_sync(0xffffffffu, s, o);
    if (lane == 0) {
        g_us2[row] = uprev - lg2f(s);
        g_f[row]   = 1.0f / s;
    }
}

// col: v_j = v_j - log2( sum_i f_i * e_ij ).  Pure FMA, no MUFU in the hot loop.
// grid = NB * RCH_F * JB_F = 512 blocks; thread handles 4 columns.
__global__ __launch_bounds__(256) void col_fast() {
    __shared__ float fs[CHK_F];
    __shared__ unsigned lastv;
    const int b     = blockIdx.x;
    const int jb    = b & (JB_F - 1);
    const int chunk = (b >> 1) & (RCH_F - 1);
    const int n     = b >> 7;
    const int j0    = (jb << 10) + (threadIdx.x << 2);   // 4 cols/thread
    const int i0    = chunk << 5;                         // 32 rows/chunk

    if (threadIdx.x < CHK_F)
        fs[threadIdx.x] = g_f[(n << 11) + i0 + threadIdx.x];
    __syncthreads();

    const __nv_bfloat16* Eb = g_E + ((size_t)(n << 11) + i0) * P + j0;
    float a0 = 0.0f, a1 = 0.0f, a2 = 0.0f, a3 = 0.0f;
#pragma unroll 4
    for (int i = 0; i < CHK_F; i += 2) {
        uint2 p0 = *(const uint2*)(Eb + (size_t)i * P);
        uint2 p1 = *(const uint2*)(Eb + (size_t)(i + 1) * P);
        const float f0 = fs[i], f1 = fs[i + 1];
        float2 lo0 = __bfloat1622float2(*(__nv_bfloat162*)&p0.x);
        float2 hi0 = __bfloat1622float2(*(__nv_bfloat162*)&p0.y);
        float2 lo1 = __bfloat1622float2(*(__nv_bfloat162*)&p1.x);
        float2 hi1 = __bfloat1622float2(*(__nv_bfloat162*)&p1.y);
        a0 = fmaf(f0, lo0.x, a0); a1 = fmaf(f0, lo0.y, a1);
        a2 = fmaf(f0, hi0.x, a2); a3 = fmaf(f0, hi0.y, a3);
        a0 = fmaf(f1, lo1.x, a0); a1 = fmaf(f1, lo1.y, a1);
        a2 = fmaf(f1, hi1.x, a2); a3 = fmaf(f1, hi1.y, a3);
    }
    float4 part = {a0, a1, a2, a3};
    *(float4*)&g_ps2[((size_t)n * RCH_F + chunk) * P + j0] = part;

    __threadfence();
    if (threadIdx.x == 0) lastv = atomicAdd(&g_tick_f[n * JB_F + jb], 1u);
    __syncthreads();
    if (lastv == RCH_F - 1) {
        __threadfence();
        float ss0 = 0.0f, ss1 = 0.0f, ss2 = 0.0f, ss3 = 0.0f;
#pragma unroll 8
        for (int c = 0; c < RCH_F; c++) {
            const float4 pp = *(const float4*)&g_ps2[((size_t)n * RCH_F + c) * P + j0];
            ss0 += pp.x; ss1 += pp.y; ss2 += pp.z; ss3 += pp.w;
        }
        const int gj = (n << 11) + j0;
        g_vs2[gj]     = g_vs2[gj]     - lg2f(ss0);
        g_vs2[gj + 1] = g_vs2[gj + 1] - lg2f(ss1);
        g_vs2[gj + 2] = g_vs2[gj + 2] - lg2f(ss2);
        g_vs2[gj + 3] = g_vs2[gj + 3] - lg2f(ss3);
        if (threadIdx.x == 0) g_tick_f[n * JB_F + jb] = 0u;
    }
}

// ---------------- pi + cost partials ----------------------------------------------
__global__ __launch_bounds__(256) void pi_cost(const float* __restrict__ C,
                                               float* __restrict__ pi) {
    __shared__ float red[256];
    const int b = blockIdx.x;
    const int n = b >> 10;
    const float4* C4 = (const float4*)C;
    float4* P4 = (float4*)pi;
    const float4* V4 = (const float4*)(g_vs2 + (n << 11));
    const size_t base = (size_t)b * 1024;

    float acc = 0.0f;
#pragma unroll
    for (int p = 0; p < 4; p++) {
        size_t f4 = base + (size_t)p * 256 + threadIdx.x;
        float4 c = C4[f4];
        int ig = (int)(f4 >> 9);
        float u = g_us2[ig];
        float4 vv = V4[f4 & (P / 4 - 1)];
        float4 pv;
        pv.x = ex2f(fmaf(c.x, -K2E, u + vv.x));
        pv.y = ex2f(fmaf(c.y, -K2E, u + vv.y));
        pv.z = ex2f(fmaf(c.z, -K2E, u + vv.z));
        pv.w = ex2f(fmaf(c.w, -K2E, u + vv.w));
        P4[f4] = pv;
        acc += pv.x * c.x + pv.y * c.y + pv.z * c.z + pv.w * c.w;
    }
    red[threadIdx.x] = acc;
    __syncthreads();
#pragma unroll
    for (int o = 128; o; o >>= 1) {
        if (threadIdx.x < o) red[threadIdx.x] += red[threadIdx.x + o];
        __syncthreads();
    }
    if (threadIdx.x == 0) g_cp[b] = red[0];
}

__global__ __launch_bounds__(256) void cost_combine(float* __restrict__ cost) {
    __shared__ float red[256];
    const int n = blockIdx.x;
    float a = 0.0f;
#pragma unroll
    for (int q = 0; q < 4; q++)
        a += g_cp[n * 1024 + q * 256 + threadIdx.x];
    red[threadIdx.x] = a;
    __syncthreads();
#pragma unroll
    for (int o = 128; o; o >>= 1) {
        if (threadIdx.x < o) red[threadIdx.x] += red[threadIdx.x + o];
        __syncthreads();
    }
    if (threadIdx.x == 0) cost[n] = red[0];
}

// ---------------- launch --------------------------------------------------------------
extern "C" void kernel_launch(void* const* d_in, const int* in_sizes, int n_in,
                              void* d_out, int out_size) {
    const float* x = (const float*)d_in[0];
    const float* y = (const float*)d_in[1];
    float* out  = (float*)d_out;
    float* cost = out;
    float* pi   = out + NB;
    float* C    = out + NB + (size_t)NB * P * P;

    init_kernel<<<32, 256>>>();
    norms_kernel<<<NB * P / 256, 256>>>(x, y);
    c_kernel<<<dim3(P / 64, P / 64, NB), dim3(16, 16)>>>(x, y, C);

    for (int it = 0; it < ITERS; it++) {
        if (it < 2) {
            row_safe<<<NB * P / 8, 256>>>(C);
            col_safe<<<NB * RCH_S * JB_S, 256>>>(C);
        } else {
            row_fast<<<NB * P / 8, 256>>>(C);
            col_fast<<<NB * RCH_F * JB_F, 256>>>();
        }
    }

    pi_cost<<<NB * 1024, 256>>>(C, pi);
    cost_combine<<<NB, 256>>>(cost);
}